// round 3
// baseline (speedup 1.0000x reference)
#include <cuda_runtime.h>

// Problem constants
constexpr int NB   = 8;      // batch
constexpr int CH   = 512;    // channels
constexpr int HW   = 4096;   // 64*64
constexpr int HW2  = 2048;   // hw/2
// conv out channels = 256, viewed as (512, 2048)

// Scratch: __device__ globals (allocation-free per harness rules)
__device__ float g_phi  [NB * CH * HW2];          // (b,256,4096) == (b,512,2048)
__device__ float g_theta[NB * CH * HW2];
__device__ float g_gbuf [NB * CH * HW2];
__device__ float g_S    [(size_t)NB * HW2 * HW2]; // (b, m, n) = scores[n,m]
__device__ float g_y2   [NB * CH * HW2];          // (b, c, m) == (b,256,4096)

// ---------------------------------------------------------------------------
// Generic tiled SGEMM: C[i,j] = sum_k A'[i,k] * B'[k,j]
//   TA=0: A is MxK row-major (lda = row stride).  TA=1: A is KxM row-major.
//   TB=0: B is KxN row-major.                     TB=1: B is NxK row-major.
// Tiles: 128x128x16, 256 threads, 8x8 per-thread microtile.
// All M%128==0, N%128==0, K%16==0 in this problem -> no bounds checks.
// EPI: C += r1 + r2 (residual add, same layout/stride as C).
// ---------------------------------------------------------------------------
template <int TA, int TB, bool EPI>
__global__ void __launch_bounds__(256) sgemm_kernel(
    const float* __restrict__ A, const float* __restrict__ Bm, float* __restrict__ Cm,
    int lda, int ldb, int ldc, int K,
    long long sA, long long sB, long long sC,
    const float* __restrict__ r1, const float* __restrict__ r2)
{
    __shared__ float As[16][132];
    __shared__ float Bs[16][132];

    const float* Ab = A  + (long long)blockIdx.z * sA;
    const float* Bb = Bm + (long long)blockIdx.z * sB;
    float*       Cb = Cm + (long long)blockIdx.z * sC;

    const int tid = threadIdx.x;
    const int m0 = blockIdx.y * 128;
    const int n0 = blockIdx.x * 128;
    const int tx = tid & 15;        // column group (8 cols)
    const int ty = tid >> 4;        // row group (8 rows)

    float acc[8][8] = {};

    for (int k0 = 0; k0 < K; k0 += 16) {
        // ---- load A tile -> As[k][m] ----
        if (TA == 0) {
            // A: MxK. Read 128 rows x 16 cols, store transposed.
            const int row = tid >> 2;            // 0..63
            const int col = (tid & 3) << 2;      // 0,4,8,12
            #pragma unroll
            for (int r = 0; r < 2; r++) {
                const float4 av = *(const float4*)(Ab + (long long)(m0 + row + r * 64) * lda + k0 + col);
                As[col + 0][row + r * 64] = av.x;
                As[col + 1][row + r * 64] = av.y;
                As[col + 2][row + r * 64] = av.z;
                As[col + 3][row + r * 64] = av.w;
            }
        } else {
            // A: KxM. Read 16 rows x 128 cols, store direct.
            const int kk = tid >> 5;             // 0..7
            const int mm = (tid & 31) << 2;      // 0..124
            #pragma unroll
            for (int r = 0; r < 2; r++) {
                *(float4*)&As[kk + r * 8][mm] =
                    *(const float4*)(Ab + (long long)(k0 + kk + r * 8) * lda + m0 + mm);
            }
        }
        // ---- load B tile -> Bs[k][n] ----
        if (TB == 0) {
            const int kk = tid >> 5;
            const int nn = (tid & 31) << 2;
            #pragma unroll
            for (int r = 0; r < 2; r++) {
                *(float4*)&Bs[kk + r * 8][nn] =
                    *(const float4*)(Bb + (long long)(k0 + kk + r * 8) * ldb + n0 + nn);
            }
        } else {
            // B: NxK. Read 128 rows x 16 cols, store transposed.
            const int row = tid >> 2;
            const int col = (tid & 3) << 2;
            #pragma unroll
            for (int r = 0; r < 2; r++) {
                const float4 bv = *(const float4*)(Bb + (long long)(n0 + row + r * 64) * ldb + k0 + col);
                Bs[col + 0][row + r * 64] = bv.x;
                Bs[col + 1][row + r * 64] = bv.y;
                Bs[col + 2][row + r * 64] = bv.z;
                Bs[col + 3][row + r * 64] = bv.w;
            }
        }
        __syncthreads();

        #pragma unroll
        for (int kk = 0; kk < 16; kk++) {
            float ra[8], rb[8];
            *(float4*)&ra[0] = *(const float4*)&As[kk][ty * 8];
            *(float4*)&ra[4] = *(const float4*)&As[kk][ty * 8 + 4];
            *(float4*)&rb[0] = *(const float4*)&Bs[kk][tx * 8];
            *(float4*)&rb[4] = *(const float4*)&Bs[kk][tx * 8 + 4];
            #pragma unroll
            for (int i = 0; i < 8; i++)
                #pragma unroll
                for (int j = 0; j < 8; j++)
                    acc[i][j] = fmaf(ra[i], rb[j], acc[i][j]);
        }
        __syncthreads();
    }

    // ---- epilogue / store ----
    #pragma unroll
    for (int i = 0; i < 8; i++) {
        const long long off = (long long)(m0 + ty * 8 + i) * ldc + n0 + tx * 8;
        #pragma unroll
        for (int j4 = 0; j4 < 2; j4++) {
            float4 o;
            o.x = acc[i][j4 * 4 + 0];
            o.y = acc[i][j4 * 4 + 1];
            o.z = acc[i][j4 * 4 + 2];
            o.w = acc[i][j4 * 4 + 3];
            if (EPI) {
                const long long roff = (long long)blockIdx.z * sC + off + j4 * 4;
                const float4 a1 = *(const float4*)(r1 + roff);
                const float4 a2 = *(const float4*)(r2 + roff);
                o.x += a1.x + a2.x;  o.y += a1.y + a2.y;
                o.z += a1.z + a2.z;  o.w += a1.w + a2.w;
            }
            *(float4*)(Cb + off + j4 * 4) = o;
        }
    }
}

// ---------------------------------------------------------------------------
// Row softmax over rows of length 2048 (S[m, :], softmax over n).
// One block of 256 threads per row; 8 elements/thread via 2x float4.
// ---------------------------------------------------------------------------
__global__ void __launch_bounds__(256) softmax_kernel(float* __restrict__ S)
{
    float* p = S + (size_t)blockIdx.x * HW2;
    const int tid = threadIdx.x;

    float4 v0 = ((const float4*)p)[tid];
    float4 v1 = ((const float4*)p)[tid + 256];

    float mx = fmaxf(fmaxf(fmaxf(v0.x, v0.y), fmaxf(v0.z, v0.w)),
                     fmaxf(fmaxf(v1.x, v1.y), fmaxf(v1.z, v1.w)));

    __shared__ float red[8];
    #pragma unroll
    for (int o = 16; o > 0; o >>= 1) mx = fmaxf(mx, __shfl_xor_sync(0xffffffffu, mx, o));
    if ((tid & 31) == 0) red[tid >> 5] = mx;
    __syncthreads();
    mx = red[0];
    #pragma unroll
    for (int i = 1; i < 8; i++) mx = fmaxf(mx, red[i]);
    __syncthreads();

    v0.x = __expf(v0.x - mx); v0.y = __expf(v0.y - mx);
    v0.z = __expf(v0.z - mx); v0.w = __expf(v0.w - mx);
    v1.x = __expf(v1.x - mx); v1.y = __expf(v1.y - mx);
    v1.z = __expf(v1.z - mx); v1.w = __expf(v1.w - mx);

    float sm = v0.x + v0.y + v0.z + v0.w + v1.x + v1.y + v1.z + v1.w;
    #pragma unroll
    for (int o = 16; o > 0; o >>= 1) sm += __shfl_xor_sync(0xffffffffu, sm, o);
    if ((tid & 31) == 0) red[tid >> 5] = sm;
    __syncthreads();
    sm = red[0];
    #pragma unroll
    for (int i = 1; i < 8; i++) sm += red[i];

    const float inv = 1.0f / sm;
    v0.x *= inv; v0.y *= inv; v0.z *= inv; v0.w *= inv;
    v1.x *= inv; v1.y *= inv; v1.z *= inv; v1.w *= inv;

    ((float4*)p)[tid]       = v0;
    ((float4*)p)[tid + 256] = v1;
}

// ---------------------------------------------------------------------------
extern "C" void kernel_launch(void* const* d_in, const int* in_sizes, int n_in,
                              void* d_out, int out_size)
{
    const float* q    = (const float*)d_in[0];
    const float* k    = (const float*)d_in[1];
    const float* v    = (const float*)d_in[2];
    const float* Wphi = (const float*)d_in[3];
    const float* Wth  = (const float*)d_in[4];
    const float* Wg   = (const float*)d_in[5];
    const float* Wm   = (const float*)d_in[6];
    float* out = (float*)d_out;

    float *phi, *theta, *gg, *S, *y2;
    cudaGetSymbolAddress((void**)&phi,   g_phi);
    cudaGetSymbolAddress((void**)&theta, g_theta);
    cudaGetSymbolAddress((void**)&gg,    g_gbuf);
    cudaGetSymbolAddress((void**)&S,     g_S);
    cudaGetSymbolAddress((void**)&y2,    g_y2);

    const dim3 blk(256);
    const long long sX  = (long long)CH * HW;      // 2097152: q/k/v/out batch stride
    const long long sP  = (long long)CH * HW2;     // 1048576: phi/theta/g/y2 batch stride
    const long long sS  = (long long)HW2 * HW2;    // 4194304: scores batch stride

    // 1) 1x1 convs: C(256x4096) = W(256x512) @ X(512x4096)       [NN]
    sgemm_kernel<0,0,false><<<dim3(32, 2, NB), blk>>>(Wphi, q, phi, CH, HW, HW, CH, 0, sX, sP, nullptr, nullptr);
    sgemm_kernel<0,0,false><<<dim3(32, 2, NB), blk>>>(Wth,  k, theta, CH, HW, HW, CH, 0, sX, sP, nullptr, nullptr);
    sgemm_kernel<0,0,false><<<dim3(32, 2, NB), blk>>>(Wg,   v, gg,    CH, HW, HW, CH, 0, sX, sP, nullptr, nullptr);

    // 2) scores: S[m,n] = sum_c phi[c,m] * theta[c,n]            [TN], K=512
    sgemm_kernel<1,0,false><<<dim3(16, 16, NB), blk>>>(phi, theta, S, HW2, HW2, HW2, CH, sP, sP, sS, nullptr, nullptr);

    // 3) softmax over n (rows of S), 8*2048 rows
    softmax_kernel<<<NB * HW2, blk>>>(S);

    // 4) y2[c,m] = sum_n g[c,n] * S'[m,n]                        [NT], K=2048
    sgemm_kernel<0,1,false><<<dim3(16, 4, NB), blk>>>(gg, S, y2, HW2, HW2, HW2, HW2, sP, sS, sP, nullptr, nullptr);

    // 5) out = W_mask(512x256) @ y3(256x4096) + q + v            [NN + residual], K=256
    sgemm_kernel<0,0,true><<<dim3(32, 4, NB), blk>>>(Wm, y2, out, 256, HW, HW, 256, 0, sP, sX, q, v);
}

// round 5
// speedup vs baseline: 3.2557x; 3.2557x over previous
#include <cuda_runtime.h>
#include <cuda_bf16.h>
#include <cstdint>

constexpr int NB  = 8;
constexpr int CH  = 512;
constexpr int HW  = 4096;
constexpr int HW2 = 2048;
constexpr int CO  = 256;

// ---------------- device scratch ----------------
__device__ __align__(256) float g_phi  [(size_t)NB * CO * HW];
__device__ __align__(256) float g_theta[(size_t)NB * CO * HW];
__device__ __align__(256) float g_S    [(size_t)NB * HW2 * HW2];
__device__ __align__(256) float g_y2   [(size_t)NB * CH * HW2];

__device__ __align__(256) __nv_bfloat16 g_qTh[(size_t)NB * HW * CH], g_qTl[(size_t)NB * HW * CH];
__device__ __align__(256) __nv_bfloat16 g_kTh[(size_t)NB * HW * CH], g_kTl[(size_t)NB * HW * CH];
__device__ __align__(256) __nv_bfloat16 g_vTh[(size_t)NB * HW * CH], g_vTl[(size_t)NB * HW * CH];
__device__ __align__(256) __nv_bfloat16 g_Wph[CO * CH], g_Wpl[CO * CH];
__device__ __align__(256) __nv_bfloat16 g_Wth[CO * CH], g_Wtl[CO * CH];
__device__ __align__(256) __nv_bfloat16 g_Wgh[CO * CH], g_Wgl[CO * CH];
__device__ __align__(256) __nv_bfloat16 g_Wmh[CH * CO], g_Wml[CH * CO];
__device__ __align__(256) __nv_bfloat16 g_gh [(size_t)NB * CH * HW2], g_gl [(size_t)NB * CH * HW2];
__device__ __align__(256) __nv_bfloat16 g_pTh[(size_t)NB * HW2 * CH], g_pTl[(size_t)NB * HW2 * CH];
__device__ __align__(256) __nv_bfloat16 g_tTh[(size_t)NB * HW2 * CH], g_tTl[(size_t)NB * HW2 * CH];
__device__ __align__(256) __nv_bfloat16 g_Sh [(size_t)NB * HW2 * HW2], g_Sl [(size_t)NB * HW2 * HW2];
__device__ __align__(256) __nv_bfloat16 g_y3h[(size_t)NB * HW * CO],  g_y3l[(size_t)NB * HW * CO];

// ---------------- helpers ----------------
__device__ __forceinline__ uint32_t s2u(const void* p) {
    uint32_t a;
    asm("{ .reg .u64 t; cvta.to.shared.u64 t, %1; cvt.u32.u64 %0, t; }" : "=r"(a) : "l"(p));
    return a;
}
__device__ __forceinline__ void bsplit(float v, __nv_bfloat16& h, __nv_bfloat16& l) {
    h = __float2bfloat16(v);
    l = __float2bfloat16(v - __bfloat162float(h));
}
__device__ __forceinline__ void ldsm4(uint32_t* r, uint32_t addr) {
    asm volatile("ldmatrix.sync.aligned.m8n8.x4.shared.b16 {%0,%1,%2,%3}, [%4];"
                 : "=r"(r[0]), "=r"(r[1]), "=r"(r[2]), "=r"(r[3]) : "r"(addr));
}
__device__ __forceinline__ void mma16816(float* d, const uint32_t* a, uint32_t b0, uint32_t b1) {
    asm volatile("mma.sync.aligned.m16n8k16.row.col.f32.bf16.bf16.f32 "
                 "{%0,%1,%2,%3}, {%4,%5,%6,%7}, {%8,%9}, {%0,%1,%2,%3};"
                 : "+f"(d[0]), "+f"(d[1]), "+f"(d[2]), "+f"(d[3])
                 : "r"(a[0]), "r"(a[1]), "r"(a[2]), "r"(a[3]), "r"(b0), "r"(b1));
}
__device__ __forceinline__ void cpasync16(uint32_t s, const void* g) {
    asm volatile("cp.async.cg.shared.global [%0], [%1], 16;" :: "r"(s), "l"(g));
}
#define CP_COMMIT() asm volatile("cp.async.commit_group;" ::: "memory")
#define CP_WAIT0()  asm volatile("cp.async.wait_group 0;" ::: "memory")

// smem layout per stage (32 KB): Ah @0, Al @8192, Bh @16384, Bl @24576.
// Row = 64 B (32 bf16), chunk = 16 B, swizzle: chunk ^= (row>>1)&3  (ldsm conflict-free)
__device__ __forceinline__ void load_stage(uint32_t sbase,
    const __nv_bfloat16* pAh, const __nv_bfloat16* pAl,
    const __nv_bfloat16* pBh, const __nv_bfloat16* pBl,
    int Ktot, int kofs, int tid)
{
    const int row = tid >> 1;                    // 0..127
    const int c0 = (tid & 1) * 2;                // chunk pair {0,1} or {2,3}
    const long long gofs = (long long)row * Ktot + kofs;
    #pragma unroll
    for (int s = 0; s < 2; s++) {
        const int c = c0 + s;
        const uint32_t soff = row * 64 + ((c ^ ((row >> 1) & 3)) << 4);
        cpasync16(sbase +         soff, pAh + gofs + c * 8);
        cpasync16(sbase + 8192  + soff, pAl + gofs + c * 8);
        cpasync16(sbase + 16384 + soff, pBh + gofs + c * 8);
        cpasync16(sbase + 24576 + soff, pBl + gofs + c * 8);
    }
}

// ---------------------------------------------------------------------------
// Split-bf16 tensor-core GEMM (warp-level mma.sync):
// D(128x128 fp32 tile) = (Ah+Al)(MxK) @ (Bh+Bl)^T(NxK), A/B K-major bf16.
// EPI: 0 = fp32 store, 1 = split-bf16 hi/lo store, 2 = fp32 + r1 + r2.
// ---------------------------------------------------------------------------
template <int EPI>
__global__ void __launch_bounds__(256) mma_gemm(
    const __nv_bfloat16* __restrict__ Ah, const __nv_bfloat16* __restrict__ Al,
    const __nv_bfloat16* __restrict__ Bh, const __nv_bfloat16* __restrict__ Bl,
    float* __restrict__ C, __nv_bfloat16* __restrict__ Ch, __nv_bfloat16* __restrict__ Cl,
    int Ktot, int ldc,
    long long sA, long long sB, long long sC,
    const float* __restrict__ r1, const float* __restrict__ r2)
{
    extern __shared__ __align__(1024) char sm[];
    const int tid = threadIdx.x;
    const int wid = tid >> 5, lane = tid & 31;
    const uint32_t sb = s2u(sm);

    const int m0 = blockIdx.y * 128;
    const int n0 = blockIdx.x * 128;
    const long long bz = blockIdx.z;

    const __nv_bfloat16* pAh = Ah + bz * sA + (long long)m0 * Ktot;
    const __nv_bfloat16* pAl = Al + bz * sA + (long long)m0 * Ktot;
    const __nv_bfloat16* pBh = Bh + bz * sB + (long long)n0 * Ktot;
    const __nv_bfloat16* pBl = Bl + bz * sB + (long long)n0 * Ktot;

    const int wm = (wid >> 1) * 32;   // warp m-offset (4 rows of warps)
    const int wn = (wid & 1) * 64;    // warp n-offset (2 cols of warps)

    float acc[2][8][4];
    #pragma unroll
    for (int i = 0; i < 2; i++)
        #pragma unroll
        for (int j = 0; j < 8; j++)
            #pragma unroll
            for (int t = 0; t < 4; t++) acc[i][j][t] = 0.0f;

    load_stage(sb, pAh, pAl, pBh, pBl, Ktot, 0, tid);
    CP_COMMIT();

    const int nch = Ktot >> 5;
    for (int ic = 0; ic < nch; ic++) {
        CP_WAIT0();
        __syncthreads();
        if (ic + 1 < nch) {
            load_stage(sb + ((ic + 1) & 1) * 32768, pAh, pAl, pBh, pBl,
                       Ktot, (ic + 1) << 5, tid);
            CP_COMMIT();
        }
        const uint32_t st = sb + (ic & 1) * 32768;
        #pragma unroll
        for (int kk = 0; kk < 32; kk += 16) {
            const int kc = (kk >> 3) + (lane >> 4);   // 16B chunk idx for this lane
            uint32_t a_h[2][4], a_l[2][4];
            #pragma unroll
            for (int mi = 0; mi < 2; mi++) {
                const int row = wm + mi * 16 + (lane & 15);
                const uint32_t ad = st + row * 64 + ((kc ^ ((row >> 1) & 3)) << 4);
                ldsm4(a_h[mi], ad);
                ldsm4(a_l[mi], ad + 8192);
            }
            #pragma unroll
            for (int jj = 0; jj < 4; jj++) {
                const int row = wn + jj * 16 + (lane & 15);
                const uint32_t bd = st + 16384 + row * 64 + ((kc ^ ((row >> 1) & 3)) << 4);
                uint32_t bh[4], bl[4];
                ldsm4(bh, bd);
                ldsm4(bl, bd + 8192);
                // bh = {b0(j0), b0(j1), b1(j0), b1(j1)} for n8-tiles j0=2jj, j1=2jj+1
                #pragma unroll
                for (int mi = 0; mi < 2; mi++) {
                    mma16816(acc[mi][jj * 2],     a_h[mi], bh[0], bh[2]);
                    mma16816(acc[mi][jj * 2 + 1], a_h[mi], bh[1], bh[3]);
                    mma16816(acc[mi][jj * 2],     a_h[mi], bl[0], bl[2]);
                    mma16816(acc[mi][jj * 2 + 1], a_h[mi], bl[1], bl[3]);
                    mma16816(acc[mi][jj * 2],     a_l[mi], bh[0], bh[2]);
                    mma16816(acc[mi][jj * 2 + 1], a_l[mi], bh[1], bh[3]);
                }
            }
        }
        __syncthreads();
    }

    // epilogue: direct stores (each thread owns (g, tg*2) pairs of the warp tile)
    const int g = lane >> 2, tg = lane & 3;
    const long long cbz = bz * sC;
    #pragma unroll
    for (int mi = 0; mi < 2; mi++) {
        #pragma unroll
        for (int j = 0; j < 8; j++) {
            const int row = m0 + wm + mi * 16 + g;
            const int col = n0 + wn + j * 8 + tg * 2;
            #pragma unroll
            for (int h = 0; h < 2; h++) {
                const long long idx = cbz + (long long)(row + h * 8) * ldc + col;
                const float d0 = acc[mi][j][h * 2];
                const float d1 = acc[mi][j][h * 2 + 1];
                if (EPI == 0) {
                    *(float2*)(C + idx) = make_float2(d0, d1);
                } else if (EPI == 2) {
                    const float2 a = *(const float2*)(r1 + idx);
                    const float2 b = *(const float2*)(r2 + idx);
                    *(float2*)(C + idx) = make_float2(d0 + a.x + b.x, d1 + a.y + b.y);
                } else {
                    __nv_bfloat16 h0, l0, h1, l1;
                    bsplit(d0, h0, l0); bsplit(d1, h1, l1);
                    *(__nv_bfloat162*)(Ch + idx) = __halves2bfloat162(h0, h1);
                    *(__nv_bfloat162*)(Cl + idx) = __halves2bfloat162(l0, l1);
                }
            }
        }
    }
}

// ---------------------------------------------------------------------------
// conversion kernels
// ---------------------------------------------------------------------------
__global__ void __launch_bounds__(256) split_kernel(const float* __restrict__ in,
                                                    __nv_bfloat16* __restrict__ hi,
                                                    __nv_bfloat16* __restrict__ lo, int n) {
    const int i = blockIdx.x * 256 + threadIdx.x;
    if (i < n) {
        __nv_bfloat16 h, l;
        bsplit(in[i], h, l);
        hi[i] = h; lo[i] = l;
    }
}

// (b, 512, 4096) -> (b, 4096, 512) hi/lo
__global__ void __launch_bounds__(256) tsplit_kernel(const float* __restrict__ in,
                                                     __nv_bfloat16* __restrict__ oh,
                                                     __nv_bfloat16* __restrict__ ol) {
    __shared__ float T[32][33];
    const int tx = threadIdx.x & 31, ty = threadIdx.x >> 5;
    const int x0 = blockIdx.x * 32, c0 = blockIdx.y * 32;
    const float* I = in + (size_t)blockIdx.z * CH * HW;
    #pragma unroll
    for (int r = 0; r < 4; r++)
        T[ty + r * 8][tx] = I[(size_t)(c0 + ty + r * 8) * HW + x0 + tx];
    __syncthreads();
    const size_t ob = (size_t)blockIdx.z * HW * CH;
    #pragma unroll
    for (int r = 0; r < 4; r++) {
        const float v = T[tx][ty + r * 8];
        __nv_bfloat16 h, l;
        bsplit(v, h, l);
        const size_t o = ob + (size_t)(x0 + ty + r * 8) * CH + c0 + tx;
        oh[o] = h; ol[o] = l;
    }
}

// phi/theta (b,256,4096) fp32 -> (b,2048,512) hi/lo: out[n][2o+h] = C[o][h*2048+n]
__global__ void __launch_bounds__(256) ptT_kernel(const float* __restrict__ in,
                                                  __nv_bfloat16* __restrict__ oh,
                                                  __nv_bfloat16* __restrict__ ol) {
    __shared__ float T0[32][33];
    __shared__ float T1[32][33];
    const int tx = threadIdx.x & 31, ty = threadIdx.x >> 5;
    const int n0 = blockIdx.x * 32, o0 = blockIdx.y * 32;
    const float* I = in + (size_t)blockIdx.z * CO * HW;
    #pragma unroll
    for (int r = 0; r < 4; r++) {
        const size_t rowb = (size_t)(o0 + ty + r * 8) * HW + n0 + tx;
        T0[ty + r * 8][tx] = I[rowb];
        T1[ty + r * 8][tx] = I[rowb + 2048];
    }
    __syncthreads();
    const size_t ob = (size_t)blockIdx.z * HW2 * CH;
    #pragma unroll
    for (int r = 0; r < 4; r++) {
        const float v0 = T0[tx][ty + r * 8];
        const float v1 = T1[tx][ty + r * 8];
        __nv_bfloat16 h0, l0, h1, l1;
        bsplit(v0, h0, l0); bsplit(v1, h1, l1);
        const size_t o = ob + (size_t)(n0 + ty + r * 8) * CH + 2 * (o0 + tx);
        *(__nv_bfloat162*)(oh + o) = __halves2bfloat162(h0, h1);
        *(__nv_bfloat162*)(ol + o) = __halves2bfloat162(l0, l1);
    }
}

// y2 (b,512,2048) fp32 -> y3T (b,4096,256) hi/lo: out[h1*2048+m][o2] = y2[2*o2+h1][m]
__global__ void __launch_bounds__(256) y3T_kernel(const float* __restrict__ in,
                                                  __nv_bfloat16* __restrict__ oh,
                                                  __nv_bfloat16* __restrict__ ol) {
    __shared__ float T[32][33];
    const int tx = threadIdx.x & 31, ty = threadIdx.x >> 5;
    const int m0 = blockIdx.x * 32, o20 = blockIdx.y * 32;
    const int b = blockIdx.z >> 1, h1 = blockIdx.z & 1;
    const float* I = in + (size_t)b * CH * HW2;
    #pragma unroll
    for (int r = 0; r < 4; r++)
        T[ty + r * 8][tx] = I[(size_t)(2 * (o20 + ty + r * 8) + h1) * HW2 + m0 + tx];
    __syncthreads();
    const size_t ob = (size_t)b * HW * CO;
    #pragma unroll
    for (int r = 0; r < 4; r++) {
        const float v = T[tx][ty + r * 8];
        __nv_bfloat16 h, l;
        bsplit(v, h, l);
        const size_t o = ob + (size_t)(h1 * 2048 + m0 + ty + r * 8) * CO + o20 + tx;
        oh[o] = h; ol[o] = l;
    }
}

// row softmax (rows of length 2048) + split to bf16 hi/lo
__global__ void __launch_bounds__(256) softmax_split_kernel(const float* __restrict__ S,
                                                            __nv_bfloat16* __restrict__ Sh,
                                                            __nv_bfloat16* __restrict__ Sl) {
    const size_t row = blockIdx.x;
    const float* p = S + row * HW2;
    const int tid = threadIdx.x;

    float4 v0 = ((const float4*)p)[tid];
    float4 v1 = ((const float4*)p)[tid + 256];

    float mx = fmaxf(fmaxf(fmaxf(v0.x, v0.y), fmaxf(v0.z, v0.w)),
                     fmaxf(fmaxf(v1.x, v1.y), fmaxf(v1.z, v1.w)));
    __shared__ float red[8];
    #pragma unroll
    for (int o = 16; o > 0; o >>= 1) mx = fmaxf(mx, __shfl_xor_sync(0xffffffffu, mx, o));
    if ((tid & 31) == 0) red[tid >> 5] = mx;
    __syncthreads();
    mx = red[0];
    #pragma unroll
    for (int i = 1; i < 8; i++) mx = fmaxf(mx, red[i]);
    __syncthreads();

    v0.x = __expf(v0.x - mx); v0.y = __expf(v0.y - mx);
    v0.z = __expf(v0.z - mx); v0.w = __expf(v0.w - mx);
    v1.x = __expf(v1.x - mx); v1.y = __expf(v1.y - mx);
    v1.z = __expf(v1.z - mx); v1.w = __expf(v1.w - mx);

    float sum = v0.x + v0.y + v0.z + v0.w + v1.x + v1.y + v1.z + v1.w;
    #pragma unroll
    for (int o = 16; o > 0; o >>= 1) sum += __shfl_xor_sync(0xffffffffu, sum, o);
    if ((tid & 31) == 0) red[tid >> 5] = sum;
    __syncthreads();
    sum = red[0];
    #pragma unroll
    for (int i = 1; i < 8; i++) sum += red[i];

    const float inv = 1.0f / sum;
    v0.x *= inv; v0.y *= inv; v0.z *= inv; v0.w *= inv;
    v1.x *= inv; v1.y *= inv; v1.z *= inv; v1.w *= inv;

    __nv_bfloat162* ph = (__nv_bfloat162*)(Sh + row * HW2);
    __nv_bfloat162* pl = (__nv_bfloat162*)(Sl + row * HW2);
    __nv_bfloat16 h0, l0, h1, l1;
    bsplit(v0.x, h0, l0); bsplit(v0.y, h1, l1);
    ph[tid * 2 + 0] = __halves2bfloat162(h0, h1); pl[tid * 2 + 0] = __halves2bfloat162(l0, l1);
    bsplit(v0.z, h0, l0); bsplit(v0.w, h1, l1);
    ph[tid * 2 + 1] = __halves2bfloat162(h0, h1); pl[tid * 2 + 1] = __halves2bfloat162(l0, l1);
    bsplit(v1.x, h0, l0); bsplit(v1.y, h1, l1);
    ph[(tid + 256) * 2 + 0] = __halves2bfloat162(h0, h1); pl[(tid + 256) * 2 + 0] = __halves2bfloat162(l0, l1);
    bsplit(v1.z, h0, l0); bsplit(v1.w, h1, l1);
    ph[(tid + 256) * 2 + 1] = __halves2bfloat162(h0, h1); pl[(tid + 256) * 2 + 1] = __halves2bfloat162(l0, l1);
}

// ---------------------------------------------------------------------------
extern "C" void kernel_launch(void* const* d_in, const int* in_sizes, int n_in,
                              void* d_out, int out_size)
{
    const float* q    = (const float*)d_in[0];
    const float* k    = (const float*)d_in[1];
    const float* v    = (const float*)d_in[2];
    const float* Wphi = (const float*)d_in[3];
    const float* Wth  = (const float*)d_in[4];
    const float* Wg   = (const float*)d_in[5];
    const float* Wm   = (const float*)d_in[6];
    float* out = (float*)d_out;

    constexpr int SMEM = 65536;
    cudaFuncSetAttribute(mma_gemm<0>, cudaFuncAttributeMaxDynamicSharedMemorySize, SMEM);
    cudaFuncSetAttribute(mma_gemm<1>, cudaFuncAttributeMaxDynamicSharedMemorySize, SMEM);
    cudaFuncSetAttribute(mma_gemm<2>, cudaFuncAttributeMaxDynamicSharedMemorySize, SMEM);

    float *phi, *theta, *S, *y2;
    cudaGetSymbolAddress((void**)&phi, g_phi);
    cudaGetSymbolAddress((void**)&theta, g_theta);
    cudaGetSymbolAddress((void**)&S, g_S);
    cudaGetSymbolAddress((void**)&y2, g_y2);
    __nv_bfloat16 *qTh, *qTl, *kTh, *kTl, *vTh, *vTl;
    __nv_bfloat16 *Wph, *Wpl, *Wthh, *Wtl, *Wgh, *Wgl, *Wmh, *Wml;
    __nv_bfloat16 *gh, *gl, *pTh, *pTl, *tTh, *tTl, *Sh, *Sl, *y3h, *y3l;
    cudaGetSymbolAddress((void**)&qTh, g_qTh); cudaGetSymbolAddress((void**)&qTl, g_qTl);
    cudaGetSymbolAddress((void**)&kTh, g_kTh); cudaGetSymbolAddress((void**)&kTl, g_kTl);
    cudaGetSymbolAddress((void**)&vTh, g_vTh); cudaGetSymbolAddress((void**)&vTl, g_vTl);
    cudaGetSymbolAddress((void**)&Wph, g_Wph); cudaGetSymbolAddress((void**)&Wpl, g_Wpl);
    cudaGetSymbolAddress((void**)&Wthh, g_Wth); cudaGetSymbolAddress((void**)&Wtl, g_Wtl);
    cudaGetSymbolAddress((void**)&Wgh, g_Wgh); cudaGetSymbolAddress((void**)&Wgl, g_Wgl);
    cudaGetSymbolAddress((void**)&Wmh, g_Wmh); cudaGetSymbolAddress((void**)&Wml, g_Wml);
    cudaGetSymbolAddress((void**)&gh, g_gh);   cudaGetSymbolAddress((void**)&gl, g_gl);
    cudaGetSymbolAddress((void**)&pTh, g_pTh); cudaGetSymbolAddress((void**)&pTl, g_pTl);
    cudaGetSymbolAddress((void**)&tTh, g_tTh); cudaGetSymbolAddress((void**)&tTl, g_tTl);
    cudaGetSymbolAddress((void**)&Sh, g_Sh);   cudaGetSymbolAddress((void**)&Sl, g_Sl);
    cudaGetSymbolAddress((void**)&y3h, g_y3h); cudaGetSymbolAddress((void**)&y3l, g_y3l);

    const dim3 blk(256);
    const long long sX  = (long long)CH * HW;    // q/k/v/out batch stride
    const long long sT  = (long long)HW * CH;    // qT/kT/vT batch stride
    const long long sP  = (long long)CO * HW;    // phi/theta/g/y2 batch stride (= CH*HW2)
    const long long sPT = (long long)HW2 * CH;   // phiT/thetaT batch stride
    const long long sS  = (long long)HW2 * HW2;  // scores batch stride
    const long long sY3 = (long long)HW * CO;    // y3T batch stride

    // 0) weight splits
    split_kernel<<<CO * CH / 256, blk>>>(Wphi, Wph, Wpl, CO * CH);
    split_kernel<<<CO * CH / 256, blk>>>(Wth,  Wthh, Wtl, CO * CH);
    split_kernel<<<CO * CH / 256, blk>>>(Wg,   Wgh, Wgl, CO * CH);
    split_kernel<<<CH * CO / 256, blk>>>(Wm,   Wmh, Wml, CH * CO);

    // 1) input transpose+split: (b,512,4096) -> (b,4096,512)
    tsplit_kernel<<<dim3(HW / 32, CH / 32, NB), blk>>>(q, qTh, qTl);
    tsplit_kernel<<<dim3(HW / 32, CH / 32, NB), blk>>>(k, kTh, kTl);
    tsplit_kernel<<<dim3(HW / 32, CH / 32, NB), blk>>>(v, vTh, vTl);

    // 2) 1x1 convs: (256x4096) = W(256x512) @ X^T; g has fused split epilogue
    mma_gemm<0><<<dim3(HW / 128, CO / 128, NB), blk, SMEM>>>(Wph, Wpl, qTh, qTl, phi, nullptr, nullptr,
                                                             CH, HW, 0, sT, sP, nullptr, nullptr);
    mma_gemm<0><<<dim3(HW / 128, CO / 128, NB), blk, SMEM>>>(Wthh, Wtl, kTh, kTl, theta, nullptr, nullptr,
                                                             CH, HW, 0, sT, sP, nullptr, nullptr);
    mma_gemm<1><<<dim3(HW / 128, CO / 128, NB), blk, SMEM>>>(Wgh, Wgl, vTh, vTl, nullptr, gh, gl,
                                                             CH, HW, 0, sT, sP, nullptr, nullptr);

    // 3) reshape-transposes for scores operands: (b,2048,512)
    ptT_kernel<<<dim3(HW2 / 32, CO / 32, NB), blk>>>(phi, pTh, pTl);
    ptT_kernel<<<dim3(HW2 / 32, CO / 32, NB), blk>>>(theta, tTh, tTl);

    // 4) scores: S[m,n] = sum_c phiT[m,c] * thetaT[n,c]   (2048x2048, K=512)
    mma_gemm<0><<<dim3(HW2 / 128, HW2 / 128, NB), blk, SMEM>>>(pTh, pTl, tTh, tTl, S, nullptr, nullptr,
                                                               CH, HW2, sPT, sPT, sS, nullptr, nullptr);

    // 5) row softmax + split
    softmax_split_kernel<<<NB * HW2, blk>>>(S, Sh, Sl);

    // 6) y2[c,m] = sum_n g[c,n] * Ssm[m,n]   (512x2048, K=2048)
    mma_gemm<0><<<dim3(HW2 / 128, CH / 128, NB), blk, SMEM>>>(gh, gl, Sh, Sl, y2, nullptr, nullptr,
                                                              HW2, HW2, sP, sS, sP, nullptr, nullptr);

    // 7) y3T transform: (b,4096,256)
    y3T_kernel<<<dim3(HW2 / 32, CO / 32, NB * 2), blk>>>(y2, y3h, y3l);

    // 8) out = Wm(512x256) @ y3(256x4096) + q + v   (K=256)
    mma_gemm<2><<<dim3(HW / 128, CH / 128, NB), blk, SMEM>>>(Wmh, Wml, y3h, y3l, out, nullptr, nullptr,
                                                             CO, HW, 0, sY3, sX, q, v);
}

// round 6
// speedup vs baseline: 3.6910x; 1.1337x over previous
#include <cuda_runtime.h>
#include <cuda_bf16.h>
#include <cstdint>

constexpr int NB  = 8;
constexpr int CH  = 512;
constexpr int HW  = 4096;
constexpr int HW2 = 2048;
constexpr int CO  = 256;

// ---------------- device scratch ----------------
__device__ __align__(256) float g_phi  [(size_t)NB * CO * HW];
__device__ __align__(256) float g_theta[(size_t)NB * CO * HW];
__device__ __align__(256) float g_S    [(size_t)NB * HW2 * HW2];
__device__ __align__(256) float g_y2   [(size_t)NB * CH * HW2];

__device__ __align__(256) __nv_bfloat16 g_qTh[(size_t)NB * HW * CH], g_qTl[(size_t)NB * HW * CH];
__device__ __align__(256) __nv_bfloat16 g_kTh[(size_t)NB * HW * CH], g_kTl[(size_t)NB * HW * CH];
__device__ __align__(256) __nv_bfloat16 g_vTh[(size_t)NB * HW * CH];
__device__ __align__(256) __nv_bfloat16 g_Wph[CO * CH], g_Wpl[CO * CH];
__device__ __align__(256) __nv_bfloat16 g_Wth[CO * CH], g_Wtl[CO * CH];
__device__ __align__(256) __nv_bfloat16 g_Wgh[CO * CH], g_Wgl[CO * CH];
__device__ __align__(256) __nv_bfloat16 g_Wmh[CH * CO], g_Wml[CH * CO];
__device__ __align__(256) __nv_bfloat16 g_gh [(size_t)NB * CH * HW2], g_gl [(size_t)NB * CH * HW2];
__device__ __align__(256) __nv_bfloat16 g_pTh[(size_t)NB * HW2 * CH], g_pTl[(size_t)NB * HW2 * CH];
__device__ __align__(256) __nv_bfloat16 g_tTh[(size_t)NB * HW2 * CH], g_tTl[(size_t)NB * HW2 * CH];
__device__ __align__(256) __nv_bfloat16 g_Sh [(size_t)NB * HW2 * HW2];
__device__ __align__(256) __nv_bfloat16 g_y3h[(size_t)NB * HW * CO];

// ---------------- helpers ----------------
__device__ __forceinline__ uint32_t s2u(const void* p) {
    uint32_t a;
    asm("{ .reg .u64 t; cvta.to.shared.u64 t, %1; cvt.u32.u64 %0, t; }" : "=r"(a) : "l"(p));
    return a;
}
__device__ __forceinline__ void bsplit(float v, __nv_bfloat16& h, __nv_bfloat16& l) {
    h = __float2bfloat16(v);
    l = __float2bfloat16(v - __bfloat162float(h));
}
__device__ __forceinline__ void ldsm4(uint32_t* r, uint32_t addr) {
    asm volatile("ldmatrix.sync.aligned.m8n8.x4.shared.b16 {%0,%1,%2,%3}, [%4];"
                 : "=r"(r[0]), "=r"(r[1]), "=r"(r[2]), "=r"(r[3]) : "r"(addr));
}
__device__ __forceinline__ void mma16816(float* d, const uint32_t* a, uint32_t b0, uint32_t b1) {
    asm volatile("mma.sync.aligned.m16n8k16.row.col.f32.bf16.bf16.f32 "
                 "{%0,%1,%2,%3}, {%4,%5,%6,%7}, {%8,%9}, {%0,%1,%2,%3};"
                 : "+f"(d[0]), "+f"(d[1]), "+f"(d[2]), "+f"(d[3])
                 : "r"(a[0]), "r"(a[1]), "r"(a[2]), "r"(a[3]), "r"(b0), "r"(b1));
}
__device__ __forceinline__ void cpasync16(uint32_t s, const void* g) {
    asm volatile("cp.async.cg.shared.global [%0], [%1], 16;" :: "r"(s), "l"(g));
}
#define CP_COMMIT() asm volatile("cp.async.commit_group;" ::: "memory")
#define CP_WAIT1()  asm volatile("cp.async.wait_group 1;" ::: "memory")

// smem per stage (32 KB): Ah @0, Al @8192, Bh @16384, Bl @24576.
// Row = 64 B (32 bf16), chunk = 16 B, swizzle: chunk ^= (row>>1)&3
template <int TERMS>
__device__ __forceinline__ void load_stage(uint32_t sbase,
    const __nv_bfloat16* pAh, const __nv_bfloat16* pAl,
    const __nv_bfloat16* pBh, const __nv_bfloat16* pBl,
    int Ktot, int kofs, int tid)
{
    const int row = tid >> 1;                    // 0..127
    const int c0 = (tid & 1) * 2;                // chunk pair
    const long long gofs = (long long)row * Ktot + kofs;
    #pragma unroll
    for (int s = 0; s < 2; s++) {
        const int c = c0 + s;
        const uint32_t soff = row * 64 + ((c ^ ((row >> 1) & 3)) << 4);
        cpasync16(sbase +         soff, pAh + gofs + c * 8);
        cpasync16(sbase + 8192  + soff, pAl + gofs + c * 8);
        cpasync16(sbase + 16384 + soff, pBh + gofs + c * 8);
        if (TERMS == 3)
            cpasync16(sbase + 24576 + soff, pBl + gofs + c * 8);
    }
}

// ---------------------------------------------------------------------------
// Split-bf16 tensor-core GEMM (mma.sync), 3-stage cp.async pipeline.
// D(128x128 fp32 tile) = (Ah+Al)(MxK) @ (Bh+Bl)^T(NxK), A/B K-major bf16.
// TERMS: 3 = hh + h*bl + al*bh; 2 = hh + al*bh (B_lo never touched).
// EPI: 0 = fp32 store, 1 = split-bf16 hi/lo store, 2 = fp32 + r1 + r2.
// ---------------------------------------------------------------------------
template <int EPI, int TERMS>
__global__ void __launch_bounds__(256) mma_gemm(
    const __nv_bfloat16* __restrict__ Ah, const __nv_bfloat16* __restrict__ Al,
    const __nv_bfloat16* __restrict__ Bh, const __nv_bfloat16* __restrict__ Bl,
    float* __restrict__ C, __nv_bfloat16* __restrict__ Ch, __nv_bfloat16* __restrict__ Cl,
    int Ktot, int ldc,
    long long sA, long long sB, long long sC,
    const float* __restrict__ r1, const float* __restrict__ r2)
{
    extern __shared__ __align__(1024) char sm[];
    const int tid = threadIdx.x;
    const int wid = tid >> 5, lane = tid & 31;
    const uint32_t sb = s2u(sm);

    const int m0 = blockIdx.y * 128;
    const int n0 = blockIdx.x * 128;
    const long long bz = blockIdx.z;

    const __nv_bfloat16* pAh = Ah + bz * sA + (long long)m0 * Ktot;
    const __nv_bfloat16* pAl = Al + bz * sA + (long long)m0 * Ktot;
    const __nv_bfloat16* pBh = Bh + bz * sB + (long long)n0 * Ktot;
    const __nv_bfloat16* pBl = (TERMS == 3) ? (Bl + bz * sB + (long long)n0 * Ktot) : nullptr;

    const int wm = (wid >> 1) * 32;
    const int wn = (wid & 1) * 64;

    float acc[2][8][4];
    #pragma unroll
    for (int i = 0; i < 2; i++)
        #pragma unroll
        for (int j = 0; j < 8; j++)
            #pragma unroll
            for (int t = 0; t < 4; t++) acc[i][j][t] = 0.0f;

    const int nch = Ktot >> 5;
    load_stage<TERMS>(sb, pAh, pAl, pBh, pBl, Ktot, 0, tid);
    CP_COMMIT();
    load_stage<TERMS>(sb + 32768, pAh, pAl, pBh, pBl, Ktot, 32, tid);
    CP_COMMIT();

    uint32_t stage = 0;     // sm offset of current stage
    uint32_t nstage = 2;    // index (mod 3) of next stage slot to fill
    for (int ic = 0; ic < nch; ic++) {
        CP_WAIT1();
        __syncthreads();
        if (ic + 2 < nch) {
            load_stage<TERMS>(sb + nstage * 32768, pAh, pAl, pBh, pBl,
                              Ktot, (ic + 2) << 5, tid);
        }
        CP_COMMIT();
        nstage = (nstage == 2) ? 0 : nstage + 1;

        const uint32_t st = sb + stage * 32768;
        stage = (stage == 2) ? 0 : stage + 1;
        #pragma unroll
        for (int kk = 0; kk < 32; kk += 16) {
            const int kc = (kk >> 3) + (lane >> 4);
            uint32_t a_h[2][4], a_l[2][4];
            #pragma unroll
            for (int mi = 0; mi < 2; mi++) {
                const int row = wm + mi * 16 + (lane & 15);
                const uint32_t ad = st + row * 64 + ((kc ^ ((row >> 1) & 3)) << 4);
                ldsm4(a_h[mi], ad);
                ldsm4(a_l[mi], ad + 8192);
            }
            #pragma unroll
            for (int jj = 0; jj < 4; jj++) {
                const int row = wn + jj * 16 + (lane & 15);
                const uint32_t bd = st + 16384 + row * 64 + ((kc ^ ((row >> 1) & 3)) << 4);
                uint32_t bh[4], bl[4];
                ldsm4(bh, bd);
                if (TERMS == 3) ldsm4(bl, bd + 8192);
                #pragma unroll
                for (int mi = 0; mi < 2; mi++) {
                    mma16816(acc[mi][jj * 2],     a_h[mi], bh[0], bh[2]);
                    mma16816(acc[mi][jj * 2 + 1], a_h[mi], bh[1], bh[3]);
                    if (TERMS == 3) {
                        mma16816(acc[mi][jj * 2],     a_h[mi], bl[0], bl[2]);
                        mma16816(acc[mi][jj * 2 + 1], a_h[mi], bl[1], bl[3]);
                    }
                    mma16816(acc[mi][jj * 2],     a_l[mi], bh[0], bh[2]);
                    mma16816(acc[mi][jj * 2 + 1], a_l[mi], bh[1], bh[3]);
                }
            }
        }
    }

    // epilogue
    const int g = lane >> 2, tg = lane & 3;
    const long long cbz = bz * sC;
    #pragma unroll
    for (int mi = 0; mi < 2; mi++) {
        #pragma unroll
        for (int j = 0; j < 8; j++) {
            const int row = m0 + wm + mi * 16 + g;
            const int col = n0 + wn + j * 8 + tg * 2;
            #pragma unroll
            for (int h = 0; h < 2; h++) {
                const long long idx = cbz + (long long)(row + h * 8) * ldc + col;
                const float d0 = acc[mi][j][h * 2];
                const float d1 = acc[mi][j][h * 2 + 1];
                if (EPI == 0) {
                    *(float2*)(C + idx) = make_float2(d0, d1);
                } else if (EPI == 2) {
                    const float2 a = *(const float2*)(r1 + idx);
                    const float2 b = *(const float2*)(r2 + idx);
                    *(float2*)(C + idx) = make_float2(d0 + a.x + b.x, d1 + a.y + b.y);
                } else {
                    __nv_bfloat16 h0, l0, h1, l1;
                    bsplit(d0, h0, l0); bsplit(d1, h1, l1);
                    *(__nv_bfloat162*)(Ch + idx) = __halves2bfloat162(h0, h1);
                    *(__nv_bfloat162*)(Cl + idx) = __halves2bfloat162(l0, l1);
                }
            }
        }
    }
}

// ---------------------------------------------------------------------------
// conversion kernels
// ---------------------------------------------------------------------------
__global__ void __launch_bounds__(256) split_kernel(const float* __restrict__ in,
                                                    __nv_bfloat16* __restrict__ hi,
                                                    __nv_bfloat16* __restrict__ lo, int n) {
    const int i = blockIdx.x * 256 + threadIdx.x;
    if (i < n) {
        __nv_bfloat16 h, l;
        bsplit(in[i], h, l);
        hi[i] = h; lo[i] = l;
    }
}

// (b, 512, 4096) -> (b, 4096, 512); lo written only if ol != nullptr
__global__ void __launch_bounds__(256) tsplit_kernel(const float* __restrict__ in,
                                                     __nv_bfloat16* __restrict__ oh,
                                                     __nv_bfloat16* __restrict__ ol) {
    __shared__ float T[32][33];
    const int tx = threadIdx.x & 31, ty = threadIdx.x >> 5;
    const int x0 = blockIdx.x * 32, c0 = blockIdx.y * 32;
    const float* I = in + (size_t)blockIdx.z * CH * HW;
    #pragma unroll
    for (int r = 0; r < 4; r++)
        T[ty + r * 8][tx] = I[(size_t)(c0 + ty + r * 8) * HW + x0 + tx];
    __syncthreads();
    const size_t ob = (size_t)blockIdx.z * HW * CH;
    #pragma unroll
    for (int r = 0; r < 4; r++) {
        const float v = T[tx][ty + r * 8];
        __nv_bfloat16 h, l;
        bsplit(v, h, l);
        const size_t o = ob + (size_t)(x0 + ty + r * 8) * CH + c0 + tx;
        oh[o] = h;
        if (ol) ol[o] = l;
    }
}

// phi/theta (b,256,4096) fp32 -> (b,2048,512) hi/lo: out[n][2o+h] = C[o][h*2048+n]
__global__ void __launch_bounds__(256) ptT_kernel(const float* __restrict__ in,
                                                  __nv_bfloat16* __restrict__ oh,
                                                  __nv_bfloat16* __restrict__ ol) {
    __shared__ float T0[32][33];
    __shared__ float T1[32][33];
    const int tx = threadIdx.x & 31, ty = threadIdx.x >> 5;
    const int n0 = blockIdx.x * 32, o0 = blockIdx.y * 32;
    const float* I = in + (size_t)blockIdx.z * CO * HW;
    #pragma unroll
    for (int r = 0; r < 4; r++) {
        const size_t rowb = (size_t)(o0 + ty + r * 8) * HW + n0 + tx;
        T0[ty + r * 8][tx] = I[rowb];
        T1[ty + r * 8][tx] = I[rowb + 2048];
    }
    __syncthreads();
    const size_t ob = (size_t)blockIdx.z * HW2 * CH;
    #pragma unroll
    for (int r = 0; r < 4; r++) {
        const float v0 = T0[tx][ty + r * 8];
        const float v1 = T1[tx][ty + r * 8];
        __nv_bfloat16 h0, l0, h1, l1;
        bsplit(v0, h0, l0); bsplit(v1, h1, l1);
        const size_t o = ob + (size_t)(n0 + ty + r * 8) * CH + 2 * (o0 + tx);
        *(__nv_bfloat162*)(oh + o) = __halves2bfloat162(h0, h1);
        *(__nv_bfloat162*)(ol + o) = __halves2bfloat162(l0, l1);
    }
}

// y2 (b,512,2048) fp32 -> y3T (b,4096,256) hi only
__global__ void __launch_bounds__(256) y3T_kernel(const float* __restrict__ in,
                                                  __nv_bfloat16* __restrict__ oh) {
    __shared__ float T[32][33];
    const int tx = threadIdx.x & 31, ty = threadIdx.x >> 5;
    const int m0 = blockIdx.x * 32, o20 = blockIdx.y * 32;
    const int b = blockIdx.z >> 1, h1 = blockIdx.z & 1;
    const float* I = in + (size_t)b * CH * HW2;
    #pragma unroll
    for (int r = 0; r < 4; r++)
        T[ty + r * 8][tx] = I[(size_t)(2 * (o20 + ty + r * 8) + h1) * HW2 + m0 + tx];
    __syncthreads();
    const size_t ob = (size_t)b * HW * CO;
    #pragma unroll
    for (int r = 0; r < 4; r++) {
        const float v = T[tx][ty + r * 8];
        const size_t o = ob + (size_t)(h1 * 2048 + m0 + ty + r * 8) * CO + o20 + tx;
        oh[o] = __float2bfloat16(v);
    }
}

// row softmax (rows of length 2048) -> bf16 hi only
__global__ void __launch_bounds__(256) softmax_split_kernel(const float* __restrict__ S,
                                                            __nv_bfloat16* __restrict__ Sh) {
    const size_t row = blockIdx.x;
    const float* p = S + row * HW2;
    const int tid = threadIdx.x;

    float4 v0 = ((const float4*)p)[tid];
    float4 v1 = ((const float4*)p)[tid + 256];

    float mx = fmaxf(fmaxf(fmaxf(v0.x, v0.y), fmaxf(v0.z, v0.w)),
                     fmaxf(fmaxf(v1.x, v1.y), fmaxf(v1.z, v1.w)));
    __shared__ float red[8];
    #pragma unroll
    for (int o = 16; o > 0; o >>= 1) mx = fmaxf(mx, __shfl_xor_sync(0xffffffffu, mx, o));
    if ((tid & 31) == 0) red[tid >> 5] = mx;
    __syncthreads();
    mx = red[0];
    #pragma unroll
    for (int i = 1; i < 8; i++) mx = fmaxf(mx, red[i]);
    __syncthreads();

    v0.x = __expf(v0.x - mx); v0.y = __expf(v0.y - mx);
    v0.z = __expf(v0.z - mx); v0.w = __expf(v0.w - mx);
    v1.x = __expf(v1.x - mx); v1.y = __expf(v1.y - mx);
    v1.z = __expf(v1.z - mx); v1.w = __expf(v1.w - mx);

    float sum = v0.x + v0.y + v0.z + v0.w + v1.x + v1.y + v1.z + v1.w;
    #pragma unroll
    for (int o = 16; o > 0; o >>= 1) sum += __shfl_xor_sync(0xffffffffu, sum, o);
    if ((tid & 31) == 0) red[tid >> 5] = sum;
    __syncthreads();
    sum = red[0];
    #pragma unroll
    for (int i = 1; i < 8; i++) sum += red[i];

    const float inv = 1.0f / sum;
    __nv_bfloat162* ph = (__nv_bfloat162*)(Sh + row * HW2);
    ph[tid * 2 + 0] = __halves2bfloat162(__float2bfloat16(v0.x * inv), __float2bfloat16(v0.y * inv));
    ph[tid * 2 + 1] = __halves2bfloat162(__float2bfloat16(v0.z * inv), __float2bfloat16(v0.w * inv));
    ph[(tid + 256) * 2 + 0] = __halves2bfloat162(__float2bfloat16(v1.x * inv), __float2bfloat16(v1.y * inv));
    ph[(tid + 256) * 2 + 1] = __halves2bfloat162(__float2bfloat16(v1.z * inv), __float2bfloat16(v1.w * inv));
}

// ---------------------------------------------------------------------------
extern "C" void kernel_launch(void* const* d_in, const int* in_sizes, int n_in,
                              void* d_out, int out_size)
{
    const float* q    = (const float*)d_in[0];
    const float* k    = (const float*)d_in[1];
    const float* v    = (const float*)d_in[2];
    const float* Wphi = (const float*)d_in[3];
    const float* Wth  = (const float*)d_in[4];
    const float* Wg   = (const float*)d_in[5];
    const float* Wm   = (const float*)d_in[6];
    float* out = (float*)d_out;

    constexpr int SMEM = 98304;   // 3 stages x 32 KB
    cudaFuncSetAttribute(mma_gemm<0,3>, cudaFuncAttributeMaxDynamicSharedMemorySize, SMEM);
    cudaFuncSetAttribute(mma_gemm<0,2>, cudaFuncAttributeMaxDynamicSharedMemorySize, SMEM);
    cudaFuncSetAttribute(mma_gemm<1,2>, cudaFuncAttributeMaxDynamicSharedMemorySize, SMEM);
    cudaFuncSetAttribute(mma_gemm<2,2>, cudaFuncAttributeMaxDynamicSharedMemorySize, SMEM);

    float *phi, *theta, *S, *y2;
    cudaGetSymbolAddress((void**)&phi, g_phi);
    cudaGetSymbolAddress((void**)&theta, g_theta);
    cudaGetSymbolAddress((void**)&S, g_S);
    cudaGetSymbolAddress((void**)&y2, g_y2);
    __nv_bfloat16 *qTh, *qTl, *kTh, *kTl, *vTh;
    __nv_bfloat16 *Wph, *Wpl, *Wthh, *Wtl, *Wgh, *Wgl, *Wmh, *Wml;
    __nv_bfloat16 *gh, *gl, *pTh, *pTl, *tTh, *tTl, *Sh, *y3h;
    cudaGetSymbolAddress((void**)&qTh, g_qTh); cudaGetSymbolAddress((void**)&qTl, g_qTl);
    cudaGetSymbolAddress((void**)&kTh, g_kTh); cudaGetSymbolAddress((void**)&kTl, g_kTl);
    cudaGetSymbolAddress((void**)&vTh, g_vTh);
    cudaGetSymbolAddress((void**)&Wph, g_Wph); cudaGetSymbolAddress((void**)&Wpl, g_Wpl);
    cudaGetSymbolAddress((void**)&Wthh, g_Wth); cudaGetSymbolAddress((void**)&Wtl, g_Wtl);
    cudaGetSymbolAddress((void**)&Wgh, g_Wgh); cudaGetSymbolAddress((void**)&Wgl, g_Wgl);
    cudaGetSymbolAddress((void**)&Wmh, g_Wmh); cudaGetSymbolAddress((void**)&Wml, g_Wml);
    cudaGetSymbolAddress((void**)&gh, g_gh);   cudaGetSymbolAddress((void**)&gl, g_gl);
    cudaGetSymbolAddress((void**)&pTh, g_pTh); cudaGetSymbolAddress((void**)&pTl, g_pTl);
    cudaGetSymbolAddress((void**)&tTh, g_tTh); cudaGetSymbolAddress((void**)&tTl, g_tTl);
    cudaGetSymbolAddress((void**)&Sh, g_Sh);
    cudaGetSymbolAddress((void**)&y3h, g_y3h);

    const dim3 blk(256);
    const long long sX  = (long long)CH * HW;
    const long long sT  = (long long)HW * CH;
    const long long sP  = (long long)CO * HW;
    const long long sPT = (long long)HW2 * CH;
    const long long sS  = (long long)HW2 * HW2;
    const long long sY3 = (long long)HW * CO;

    // 0) weight splits
    split_kernel<<<CO * CH / 256, blk>>>(Wphi, Wph, Wpl, CO * CH);
    split_kernel<<<CO * CH / 256, blk>>>(Wth,  Wthh, Wtl, CO * CH);
    split_kernel<<<CO * CH / 256, blk>>>(Wg,   Wgh, Wgl, CO * CH);
    split_kernel<<<CH * CO / 256, blk>>>(Wm,   Wmh, Wml, CH * CO);

    // 1) input transpose+split (v: hi only)
    tsplit_kernel<<<dim3(HW / 32, CH / 32, NB), blk>>>(q, qTh, qTl);
    tsplit_kernel<<<dim3(HW / 32, CH / 32, NB), blk>>>(k, kTh, kTl);
    tsplit_kernel<<<dim3(HW / 32, CH / 32, NB), blk>>>(v, vTh, nullptr);

    // 2) 1x1 convs (phi/theta 3-term; g 2-term with fused split epilogue)
    mma_gemm<0,3><<<dim3(HW / 128, CO / 128, NB), blk, SMEM>>>(Wph, Wpl, qTh, qTl, phi, nullptr, nullptr,
                                                               CH, HW, 0, sT, sP, nullptr, nullptr);
    mma_gemm<0,3><<<dim3(HW / 128, CO / 128, NB), blk, SMEM>>>(Wthh, Wtl, kTh, kTl, theta, nullptr, nullptr,
                                                               CH, HW, 0, sT, sP, nullptr, nullptr);
    mma_gemm<1,2><<<dim3(HW / 128, CO / 128, NB), blk, SMEM>>>(Wgh, Wgl, vTh, nullptr, nullptr, gh, gl,
                                                               CH, HW, 0, sT, sP, nullptr, nullptr);

    // 3) reshape-transposes for scores operands
    ptT_kernel<<<dim3(HW2 / 32, CO / 32, NB), blk>>>(phi, pTh, pTl);
    ptT_kernel<<<dim3(HW2 / 32, CO / 32, NB), blk>>>(theta, tTh, tTl);

    // 4) scores (3-term): S[m,n] = sum_c phiT[m,c] * thetaT[n,c]
    mma_gemm<0,3><<<dim3(HW2 / 128, HW2 / 128, NB), blk, SMEM>>>(pTh, pTl, tTh, tTl, S, nullptr, nullptr,
                                                                 CH, HW2, sPT, sPT, sS, nullptr, nullptr);

    // 5) row softmax -> bf16 hi
    softmax_split_kernel<<<NB * HW2, blk>>>(S, Sh);

    // 6) attn apply (2-term): y2[c,m] = sum_n g[c,n] * Ssm[m,n]
    mma_gemm<0,2><<<dim3(HW2 / 128, CH / 128, NB), blk, SMEM>>>(gh, gl, Sh, nullptr, y2, nullptr, nullptr,
                                                                HW2, HW2, sP, sS, sP, nullptr, nullptr);

    // 7) y3T transform (hi only)
    y3T_kernel<<<dim3(HW2 / 32, CO / 32, NB * 2), blk>>>(y2, y3h);

    // 8) mask conv (2-term) + residual: out = Wm @ y3 + q + v
    mma_gemm<2,2><<<dim3(HW / 128, CH / 128, NB), blk, SMEM>>>(Wmh, Wml, y3h, nullptr, out, nullptr, nullptr,
                                                               CO, HW, 0, sY3, sX, q, v);
}